// round 16
// baseline (speedup 1.0000x reference)
#include <cuda_runtime.h>
#include <cuda_bf16.h>
#include <cuda_fp16.h>
#include <cstdint>

#define B_    2
#define S_    2048
#define H_    2048
#define NH    16
#define HD    128
#define MTOT  (B_ * S_)           // 4096
#define SCALE 11.313708498984761f // sqrt(128)
#define HH    ((size_t)H_ * H_)

// 3-term GEMM tiling: M=64, N=128, BK=32, 2 CTAs/SM
#define BK3     32
#define NCH3    (H_ / BK3)            // 64
#define TS3     40
#define AT3B    (64 * TS3 * 2)        // 5120  (A tile: 64 rows)
#define WT3B    (128 * TS3 * 2)       // 10240 (W tile: 128 rows)
#define BUF3B   (2 * AT3B + 2 * WT3B) // 30720
// 1-term GEMM tiling (BK=64, 2 CTAs/SM)
#define BK1     64
#define NCH1    (H_ / BK1)            // 32
#define TS1     72
#define TILE1B  (128 * TS1 * 2)       // 18432
#define BUF1B   (2 * TILE1B)          // 36864
#define OUT_SMEM (2 * BUF1B)          // 73728  (also covers qkv: 2*30720 and epilogues)

// Attention smem
#define AST 136
#define ATILE  (128 * AST)
#define ATILE2 (ATILE * 2)
#define ATTN_SMEM (6 * ATILE2)        // 208896

// Prep: 8 floats per thread
#define PREP_XB ((MTOT * H_) / 2048)  // 4096
#define PREP_WB ((int)(HH / 2048))    // 2048

// ---------------------------------------------------------------------------
// Device scratch
// ---------------------------------------------------------------------------
__device__ __nv_bfloat16 g_xh[(size_t)MTOT * H_];
__device__ __nv_bfloat16 g_xl[(size_t)MTOT * H_];
__device__ __nv_bfloat16 g_wh[2ull * HH];
__device__ __nv_bfloat16 g_wl[2ull * HH];
__device__ __half g_xf [(size_t)MTOT * H_];
__device__ __half g_wvf[HH];
__device__ __half g_wof[HH];
__device__ __half g_cf [(size_t)MTOT * H_];
__device__ __half g_qh[(size_t)MTOT * H_];   // q*SCALE fp16 hi/lo (post-RoPE)
__device__ __half g_ql[(size_t)MTOT * H_];
__device__ __half g_kh[(size_t)MTOT * H_];
__device__ __half g_kl[(size_t)MTOT * H_];
__device__ __half g_vh[(size_t)MTOT * H_];

// ---------------------------------------------------------------------------
// PTX helpers
// ---------------------------------------------------------------------------
__device__ __forceinline__ uint32_t smem_u32(const void* p) {
    uint32_t a;
    asm("{ .reg .u64 t; cvta.to.shared.u64 t, %1; cvt.u32.u64 %0, t; }"
        : "=r"(a) : "l"(p));
    return a;
}

#define LDSM4(r, a) \
    asm volatile("ldmatrix.sync.aligned.m8n8.x4.shared.b16 {%0,%1,%2,%3}, [%4];" \
        : "=r"((r)[0]), "=r"((r)[1]), "=r"((r)[2]), "=r"((r)[3]) : "r"(a))
#define LDSM4T(r, a) \
    asm volatile("ldmatrix.sync.aligned.m8n8.x4.trans.shared.b16 {%0,%1,%2,%3}, [%4];" \
        : "=r"((r)[0]), "=r"((r)[1]), "=r"((r)[2]), "=r"((r)[3]) : "r"(a))

#define MMAB(d, a, b0v, b1v) \
    asm volatile("mma.sync.aligned.m16n8k16.row.col.f32.bf16.bf16.f32 " \
        "{%0,%1,%2,%3},{%4,%5,%6,%7},{%8,%9},{%0,%1,%2,%3};" \
        : "+f"((d)[0]), "+f"((d)[1]), "+f"((d)[2]), "+f"((d)[3]) \
        : "r"((a)[0]), "r"((a)[1]), "r"((a)[2]), "r"((a)[3]), \
          "r"(b0v), "r"(b1v))
#define MMAH(d, a, b0v, b1v) \
    asm volatile("mma.sync.aligned.m16n8k16.row.col.f32.f16.f16.f32 " \
        "{%0,%1,%2,%3},{%4,%5,%6,%7},{%8,%9},{%0,%1,%2,%3};" \
        : "+f"((d)[0]), "+f"((d)[1]), "+f"((d)[2]), "+f"((d)[3]) \
        : "r"((a)[0]), "r"((a)[1]), "r"((a)[2]), "r"((a)[3]), \
          "r"(b0v), "r"(b1v))

#define CPA16(dst, src) \
    asm volatile("cp.async.cg.shared.global [%0], [%1], 16;" \
        :: "r"(dst), "l"(src) : "memory")
#define CPA_COMMIT() asm volatile("cp.async.commit_group;" ::: "memory")
#define CPA_WAIT1()  asm volatile("cp.async.wait_group 1;" ::: "memory")
#define CPA_WAIT0()  asm volatile("cp.async.wait_group 0;" ::: "memory")

// ---------------------------------------------------------------------------
// 3-term split-bf16 GEMM, M=64 x N=128 tile (Q,K projections)
// Warps: 4 along M (16 rows each) x 2 along N (64 cols each).
// ---------------------------------------------------------------------------
__device__ __forceinline__ void prefetch3(
    uint32_t sdst, const char* a0, const char* a1,
    const char* b0, const char* b1, int kc)
{
    const int tid = threadIdx.x;
    #pragma unroll
    for (int it = 0; it < 6; it++) {
        int idx = it * 256 + tid;
        if (idx < 512) {                       // A tiles: 64 rows x 2 (hi/lo)
            int tl = idx >> 8;
            int r  = (idx >> 2) & 63;
            int cv = idx & 3;
            const char* src = (tl ? a1 : a0)
                + (size_t)r * (H_ * 2) + kc * (BK3 * 2) + cv * 16;
            uint32_t dst = sdst + (uint32_t)tl * AT3B
                + (uint32_t)(r * TS3 + cv * 8) * 2;
            CPA16(dst, src);
        } else {                               // W tiles: 128 rows x 2
            int j  = idx - 512;
            int tl = j >> 9;
            int r  = (j >> 2) & 127;
            int cv = j & 3;
            const char* src = (tl ? b1 : b0)
                + (size_t)r * (H_ * 2) + kc * (BK3 * 2) + cv * 16;
            uint32_t dst = sdst + 2 * AT3B + (uint32_t)tl * WT3B
                + (uint32_t)(r * TS3 + cv * 8) * 2;
            CPA16(dst, src);
        }
    }
    CPA_COMMIT();
}

__device__ __forceinline__ void gemm_main3(
    const __nv_bfloat16* __restrict__ Ah, const __nv_bfloat16* __restrict__ Al,
    const __nv_bfloat16* __restrict__ Wh, const __nv_bfloat16* __restrict__ Wl,
    int m0, int n0, float acc[8][4])
{
    extern __shared__ char smx[];
    const uint32_t sbase = smem_u32(smx);
    const char* a0 = (const char*)(Ah + (size_t)m0 * H_);
    const char* a1 = (const char*)(Al + (size_t)m0 * H_);
    const char* b0 = (const char*)(Wh + (size_t)n0 * H_);
    const char* b1 = (const char*)(Wl + (size_t)n0 * H_);
    const int lane = threadIdx.x & 31;
    const int warp = threadIdx.x >> 5;
    const int wm = warp & 3;        // 4 warps along M (16 rows each)
    const int wn = warp >> 2;       // 2 warps along N (64 cols each)
    const int lrow = lane & 15;
    const int lk8  = (lane >> 4) * 8;

    prefetch3(sbase, a0, a1, b0, b1, 0);

    for (int c = 0; c < NCH3; c++) {
        const uint32_t sbuf = sbase + (uint32_t)(c & 1) * BUF3B;
        if (c + 1 < NCH3) {
            prefetch3(sbase + (uint32_t)((c + 1) & 1) * BUF3B, a0, a1, b0, b1, c + 1);
            CPA_WAIT1();
        } else {
            CPA_WAIT0();
        }
        __syncthreads();

        #pragma unroll
        for (int ks = 0; ks < 2; ks++) {
            const int koff = ks * 16 + lk8;
            uint32_t ah[4], al[4];
            {
                uint32_t addr = sbuf +
                    (uint32_t)((wm * 16 + lrow) * TS3 + koff) * 2;
                LDSM4(ah, addr);
                LDSM4(al, addr + AT3B);
            }
            const uint32_t bbase = sbuf + 2 * AT3B +
                (uint32_t)((wn * 64 + lrow) * TS3 + koff) * 2;
            uint32_t bh[2][4];
            LDSM4(bh[0], bbase);
            #pragma unroll
            for (int nb = 0; nb < 4; nb++) {
                const int cur = nb & 1, nxt = cur ^ 1;
                const uint32_t baddr = bbase + (uint32_t)(nb * 16 * TS3) * 2;
                if (nb < 3)
                    LDSM4(bh[nxt], baddr + (uint32_t)(16 * TS3) * 2);
                MMAB(acc[2*nb],   ah, bh[cur][0], bh[cur][2]);
                MMAB(acc[2*nb+1], ah, bh[cur][1], bh[cur][3]);
                uint32_t bl[4];
                LDSM4(bl, baddr + WT3B);
                MMAB(acc[2*nb],   al, bh[cur][0], bh[cur][2]);
                MMAB(acc[2*nb+1], al, bh[cur][1], bh[cur][3]);
                MMAB(acc[2*nb],   ah, bl[0], bl[2]);
                MMAB(acc[2*nb+1], ah, bl[1], bl[3]);
            }
        }
        __syncthreads();
    }
}

// ---------------------------------------------------------------------------
// 1-term fp16 GEMM (V projection, output projection) — BK=64, M=128
// ---------------------------------------------------------------------------
__device__ __forceinline__ void prefetch1(
    uint32_t sdst, const char* s0, const char* s1, int kc)
{
    const char* srcs[2] = { s0, s1 };
    const int tid = threadIdx.x;
    #pragma unroll
    for (int it = 0; it < 8; it++) {
        int idx  = it * 256 + tid;
        int tile = idx >> 10;
        int r    = (idx >> 3) & 127;
        int cv   = idx & 7;
        const char* src = srcs[tile] + (size_t)r * (H_ * 2) + kc * (BK1 * 2) + cv * 16;
        uint32_t dst = sdst + tile * TILE1B + (uint32_t)(r * TS1 + cv * 8) * 2;
        CPA16(dst, src);
    }
    CPA_COMMIT();
}

__device__ __forceinline__ void gemm_main1(
    const __half* __restrict__ A, const __half* __restrict__ W,
    int m0, int n0, float acc[2][8][4])
{
    extern __shared__ char smx[];
    const uint32_t sbase = smem_u32(smx);
    const char* a0 = (const char*)(A + (size_t)m0 * H_);
    const char* b0 = (const char*)(W + (size_t)n0 * H_);
    const int lane = threadIdx.x & 31;
    const int warp = threadIdx.x >> 5;
    const int wm = warp & 3;
    const int wn = warp >> 2;
    const int lrow = lane & 15;
    const int lk8  = (lane >> 4) * 8;

    prefetch1(sbase, a0, b0, 0);

    for (int c = 0; c < NCH1; c++) {
        const uint32_t sbuf = sbase + (uint32_t)(c & 1) * BUF1B;
        if (c + 1 < NCH1) {
            prefetch1(sbase + (uint32_t)((c + 1) & 1) * BUF1B, a0, b0, c + 1);
            CPA_WAIT1();
        } else {
            CPA_WAIT0();
        }
        __syncthreads();

        #pragma unroll
        for (int ks = 0; ks < 4; ks++) {
            const int koff = ks * 16 + lk8;
            uint32_t ah[2][4];
            #pragma unroll
            for (int g = 0; g < 2; g++) {
                uint32_t addr = sbuf +
                    (uint32_t)((wm * 32 + g * 16 + lrow) * TS1 + koff) * 2;
                LDSM4(ah[g], addr);
            }
            const uint32_t bbase = sbuf + TILE1B +
                (uint32_t)((wn * 64 + lrow) * TS1 + koff) * 2;
            uint32_t bb[2][4];
            LDSM4(bb[0], bbase);
            #pragma unroll
            for (int nb = 0; nb < 4; nb++) {
                const int cur = nb & 1, nxt = cur ^ 1;
                if (nb < 3)
                    LDSM4(bb[nxt], bbase + (uint32_t)((nb + 1) * 16 * TS1) * 2);
                MMAH(acc[0][2*nb],   ah[0], bb[cur][0], bb[cur][2]);
                MMAH(acc[0][2*nb+1], ah[0], bb[cur][1], bb[cur][3]);
                MMAH(acc[1][2*nb],   ah[1], bb[cur][0], bb[cur][2]);
                MMAH(acc[1][2*nb+1], ah[1], bb[cur][1], bb[cur][3]);
            }
        }
        __syncthreads();
    }
}

// acc -> smem, M=128 variant (V/out projections)
__device__ __forceinline__ void acc_to_smem(float acc[2][8][4], float* smf)
{
    const int lane = threadIdx.x & 31;
    const int warp = threadIdx.x >> 5;
    const int wm = warp & 3, wn = warp >> 2;
    #pragma unroll
    for (int g = 0; g < 2; g++) {
        #pragma unroll
        for (int j = 0; j < 8; j++) {
            int row = wm * 32 + g * 16 + (lane >> 2);
            int col = wn * 64 + (j >> 1) * 16 + (j & 1) * 8 + 2 * (lane & 3);
            smf[row * 132 + col]           = acc[g][j][0];
            smf[row * 132 + col + 1]       = acc[g][j][1];
            smf[(row + 8) * 132 + col]     = acc[g][j][2];
            smf[(row + 8) * 132 + col + 1] = acc[g][j][3];
        }
    }
}

// acc -> smem, M=64 variant (QK projections)
__device__ __forceinline__ void acc_to_smem64(float acc[8][4], float* smf)
{
    const int lane = threadIdx.x & 31;
    const int warp = threadIdx.x >> 5;
    const int wm = warp & 3, wn = warp >> 2;
    #pragma unroll
    for (int j = 0; j < 8; j++) {
        int row = wm * 16 + (lane >> 2);
        int col = wn * 64 + (j >> 1) * 16 + (j & 1) * 8 + 2 * (lane & 3);
        smf[row * 132 + col]           = acc[j][0];
        smf[row * 132 + col + 1]       = acc[j][1];
        smf[(row + 8) * 132 + col]     = acc[j][2];
        smf[(row + 8) * 132 + col + 1] = acc[j][3];
    }
}

// ---------------------------------------------------------------------------
// Fused QKV projection. z<2: 3-term bf16 GEMM (M=64 tiles) + RoPE -> fp16
// hi/lo (q pre-scaled). z=2: 1-term fp16 GEMM (M=128, y<32) -> v fp16.
// Grid (16, 64, 3): 2048 QK tiles + 512 V tiles + 512 no-ops.
// ---------------------------------------------------------------------------
__global__ __launch_bounds__(256, 2)
void qkv_mma_kernel(const float* __restrict__ cs, const float* __restrict__ sn)
{
    const int z    = blockIdx.z;
    const int head = blockIdx.x;
    const int n0   = head * 128;
    extern __shared__ char smx[];
    float* smf = (float*)smx;
    const int t = threadIdx.x;

    if (z < 2) {
        const int m0 = blockIdx.y * 64;
        float acc[8][4];
        #pragma unroll
        for (int j = 0; j < 8; j++)
            #pragma unroll
            for (int e = 0; e < 4; e++) acc[j][e] = 0.f;

        gemm_main3(g_xh, g_xl, g_wh + (size_t)z * HH, g_wl + (size_t)z * HH,
                   m0, n0, acc);

        acc_to_smem64(acc, smf);   // 64*132*4 = 33792 <= OUT_SMEM
        __syncthreads();

        const int r    = t >> 2;           // 0..63
        const int quad = t & 3;
        const int dh   = (quad & 1) * 32;
        const int j0   = (quad >> 1) * 16;
        const int m = m0 + r;
        const int s = m & (S_ - 1);
        const int b = m >> 11;
        const size_t rowbase = ((size_t)(b * NH + head) * S_ + s) * HD;

        __half* dsth = ((z == 0) ? g_qh : g_kh) + rowbase;
        __half* dstl = ((z == 0) ? g_ql : g_kl) + rowbase;
        const float sc = (z == 0) ? SCALE : 1.0f;
        const float* crow = cs + (size_t)s * HD;
        const float* srow = sn + (size_t)s * HD;
        #pragma unroll
        for (int jj = 0; jj < 16; jj++) {
            int j = j0 + jj;
            float lo = smf[r * 132 + dh + j];
            float hi = smf[r * 132 + dh + j + 64];
            float olo = (lo * crow[dh + j]      - hi * srow[dh + j])      * sc;
            float ohi = (hi * crow[dh + j + 64] + lo * srow[dh + j + 64]) * sc;
            __half a  = __float2half_rn(olo);
            __half bq = __float2half_rn(ohi);
            dsth[dh + j]      = a;
            dsth[dh + j + 64] = bq;
            dstl[dh + j]      = __float2half_rn(olo - __half2float(a));
            dstl[dh + j + 64] = __float2half_rn(ohi - __half2float(bq));
        }
    } else {
        if (blockIdx.y >= 32) return;      // only 32 M-tiles of 128 for V
        const int m0 = blockIdx.y * 128;
        float acc[2][8][4];
        #pragma unroll
        for (int g = 0; g < 2; g++)
            #pragma unroll
            for (int j = 0; j < 8; j++)
                #pragma unroll
                for (int e = 0; e < 4; e++) acc[g][j][e] = 0.f;

        gemm_main1(g_xf, g_wvf, m0, n0, acc);

        acc_to_smem(acc, smf);   // 67584 <= 73728
        __syncthreads();

        const int r  = t >> 1;
        const int dh = (t & 1) * 32;
        const int m  = m0 + r;
        const int s  = m & (S_ - 1);
        const int b  = m >> 11;
        __half* dst = g_vh + ((size_t)(b * NH + head) * S_ + s) * HD;
        #pragma unroll
        for (int j = 0; j < 32; j++) {
            dst[dh + j]      = __float2half_rn(smf[r * 132 + dh + j]);
            dst[dh + j + 64] = __float2half_rn(smf[r * 132 + dh + j + 64]);
        }
    }
}

// ---------------------------------------------------------------------------
// Output projection
// ---------------------------------------------------------------------------
__global__ __launch_bounds__(256, 2)
void outproj_mma_kernel(float* __restrict__ out)
{
    const int m0 = blockIdx.y * 128;
    const int n0 = blockIdx.x * 128;

    float acc[2][8][4];
    #pragma unroll
    for (int g = 0; g < 2; g++)
        #pragma unroll
        for (int j = 0; j < 8; j++)
            #pragma unroll
            for (int e = 0; e < 4; e++) acc[g][j][e] = 0.f;

    gemm_main1(g_cf, g_wof, m0, n0, acc);

    const int lane = threadIdx.x & 31;
    const int warp = threadIdx.x >> 5;
    const int wm = warp & 3, wn = warp >> 2;
    #pragma unroll
    for (int g = 0; g < 2; g++) {
        #pragma unroll
        for (int j = 0; j < 8; j++) {
            size_t row = (size_t)m0 + wm * 32 + g * 16 + (lane >> 2);
            int col = n0 + wn * 64 + (j >> 1) * 16 + (j & 1) * 8 + 2 * (lane & 3);
            *(float2*)&out[row * H_ + col] =
                make_float2(acc[g][j][0], acc[g][j][1]);
            *(float2*)&out[(row + 8) * H_ + col] =
                make_float2(acc[g][j][2], acc[g][j][3]);
        }
    }
}

// ---------------------------------------------------------------------------
// Fused prep — 8 floats/thread, 16B stores per destination array
// ---------------------------------------------------------------------------
__global__ void prep_kernel(const float* __restrict__ x,
                            const float* __restrict__ Wq,
                            const float* __restrict__ Wk,
                            const float* __restrict__ Wv,
                            const float* __restrict__ Wo)
{
    const int bid = blockIdx.x;
    const int t   = threadIdx.x;

    union PB { __nv_bfloat16 b[8]; uint4 u; };
    union PH { __half h[8]; uint4 u; };

    if (bid < PREP_XB) {
        size_t i = (size_t)bid * 256 + t;
        float4 v0 = ((const float4*)x)[2 * i];
        float4 v1 = ((const float4*)x)[2 * i + 1];
        float f[8] = { v0.x, v0.y, v0.z, v0.w, v1.x, v1.y, v1.z, v1.w };
        PB ph, pl; PH pf;
        #pragma unroll
        for (int j = 0; j < 8; j++) {
            ph.b[j] = __float2bfloat16(f[j]);
            pl.b[j] = __float2bfloat16(f[j] - __bfloat162float(ph.b[j]));
            pf.h[j] = __float2half_rn(f[j]);
        }
        ((uint4*)g_xh)[i] = ph.u;
        ((uint4*)g_xl)[i] = pl.u;
        ((uint4*)g_xf)[i] = pf.u;
    } else if (bid < PREP_XB + 2 * PREP_WB) {
        int wsel = (bid - PREP_XB) / PREP_WB;          // 0=Wq, 1=Wk
        size_t i = (size_t)((bid - PREP_XB) % PREP_WB) * 256 + t;
        const float* W = wsel ? Wk : Wq;
        float4 v0 = ((const float4*)W)[2 * i];
        float4 v1 = ((const float4*)W)[2 * i + 1];
        float f[8] = { v0.x, v0.y, v0.z, v0.w, v1.x, v1.y, v1.z, v1.w };
        PB ph, pl;
        #pragma unroll
        for (int j = 0; j < 8; j++) {
            ph.b[j] = __float2bfloat16(f[j]);
            pl.b[j] = __float2bfloat16(f[j] - __bfloat162float(ph.b[j]));
        }
        size_t off = (size_t)wsel * (HH / 8);           // in uint4 units
        ((uint4*)g_wh)[off + i] = ph.u;
        ((uint4*)g_wl)[off + i] = pl.u;
    } else {
        int wsel = (bid - PREP_XB - 2 * PREP_WB) / PREP_WB;  // 0=Wv, 1=Wo
        size_t i = (size_t)((bid - PREP_XB - 2 * PREP_WB) % PREP_WB) * 256 + t;
        const float* W = wsel ? Wo : Wv;
        __half* dst = wsel ? g_wof : g_wvf;
        float4 v0 = ((const float4*)W)[2 * i];
        float4 v1 = ((const float4*)W)[2 * i + 1];
        PH pf;
        pf.h[0] = __float2half_rn(v0.x); pf.h[1] = __float2half_rn(v0.y);
        pf.h[2] = __float2half_rn(v0.z); pf.h[3] = __float2half_rn(v0.w);
        pf.h[4] = __float2half_rn(v1.x); pf.h[5] = __float2half_rn(v1.y);
        pf.h[6] = __float2half_rn(v1.z); pf.h[7] = __float2half_rn(v1.w);
        ((uint4*)dst)[i] = pf.u;
    }
}

// ---------------------------------------------------------------------------
// Attention step body (templated on diagonal handling)
// ---------------------------------------------------------------------------
template<bool DIAG>
__device__ __forceinline__ void attn_step(
    uint32_t sKh_u, uint32_t sKl_u, uint32_t sVh_u,
    uint32_t (&qfh)[8][4], uint32_t (&qfl)[8][4],
    float (&o)[16][4], float (&mr)[2], float (&lr_)[2],
    int warp, int krow_b, int kcol_b, int vrow_b, int vcol_b,
    int myrow, int mycol, int kb, int grow0)
{
    float sf[16][4];
    #pragma unroll
    for (int j = 0; j < 16; j++)
        #pragma unroll
        for (int e = 0; e < 4; e++) sf[j][e] = 0.f;

#define QK_BLOCK(jj, ks)                                                        \
    do {                                                                        \
        int col = (ks) * 16 + kcol_b;                                           \
        uint32_t so0 = (uint32_t)((((jj)    ) * 16 + krow_b) * AST + col) * 2;  \
        uint32_t so1 = (uint32_t)((((jj) + 1) * 16 + krow_b) * AST + col) * 2;  \
        uint32_t kfh0[4], kfl0[4], kfh1[4], kfl1[4];                            \
        LDSM4(kfh0, sKh_u + so0);                                               \
        LDSM4(kfh1, sKh_u + so1);                                               \
        LDSM4(kfl0, sKl_u + so0);                                               \
        LDSM4(kfl1, sKl_u + so1);                                               \
        MMAH(sf[2*(jj)],   qfh[ks], kfh0[0], kfh0[1]);                          \
        MMAH(sf[2*(jj)+1], qfh[ks], kfh0[2], kfh0[3]);                          \
        MMAH(sf[2*(jj)+2], qfh[ks], kfh1[0], kfh1[1]);                          \
        MMAH(sf[2*(jj)+3], qfh[ks], kfh1[2], kfh1[3]);                          \
        MMAH(sf[2*(jj)],   qfh[ks], kfl0[0], kfl0[1]);                          \
        MMAH(sf[2*(jj)+1], qfh[ks], kfl0[2], kfl0[3]);                          \
        MMAH(sf[2*(jj)+2], qfh[ks], kfl1[0], kfl1[1]);                          \
        MMAH(sf[2*(jj)+3], qfh[ks], kfl1[2], kfl1[3]);                          \
        MMAH(sf[2*(jj)],   qfl[ks], kfh0[0], kfh0[1]);                          \
        MMAH(sf[2*(jj)+1], qfl[ks], kfh0[2], kfh0[3]);                          \
        MMAH(sf[2*(jj)+2], qfl[ks], kfh1[0], kfh1[1]);                          \
        MMAH(sf[2*(jj)+3], qfl[ks], kfh1[2], kfh1[3]);                          \
    } while (0)

    if (DIAG) {
        #pragma unroll
        for (int ks = 0; ks < 8; ks++)
            for (int jj = 0; jj <= warp; jj += 2)
                QK_BLOCK(jj, ks);
    } else {
        #pragma unroll
        for (int ks = 0; ks < 8; ks++)
            #pragma unroll
            for (int jj = 0; jj < 8; jj += 2)
                QK_BLOCK(jj, ks);
    }
#undef QK_BLOCK

    #pragma unroll
    for (int rr = 0; rr < 2; rr++) {
        const int grow = grow0 + rr * 8;
        float mx = -1e30f;
        #pragma unroll
        for (int j = 0; j < 16; j++) {
            #pragma unroll
            for (int e = 0; e < 2; e++) {
                float v = sf[j][rr * 2 + e];
                if (DIAG && (kb + j * 8 + mycol + e) > grow) v = -1e30f;
                sf[j][rr * 2 + e] = v;
                mx = fmaxf(mx, v);
            }
        }
        mx = fmaxf(mx, __shfl_xor_sync(0xffffffffu, mx, 1));
        mx = fmaxf(mx, __shfl_xor_sync(0xffffffffu, mx, 2));
        float mnew  = fmaxf(mr[rr], mx);
        float alpha = __expf(mr[rr] - mnew);
        mr[rr] = mnew;
        float ls = 0.f;
        #pragma unroll
        for (int j = 0; j < 16; j++) {
            #pragma unroll
            for (int e = 0; e < 2; e++) {
                float p = __expf(sf[j][rr * 2 + e] - mnew);
                sf[j][rr * 2 + e] = p;
                ls += p;
            }
        }
        ls += __shfl_xor_sync(0xffffffffu, ls, 1);
        ls += __shfl_xor_sync(0xffffffffu, ls, 2);
        lr_[rr] = lr_[rr] * alpha + ls;
        #pragma unroll
        for (int j = 0; j < 16; j++) {
            o[j][rr * 2]     *= alpha;
            o[j][rr * 2 + 1] *= alpha;
        }
    }

#define PV_BLOCK(j)                                                             \
    do {                                                                        \
        uint32_t pf[4];                                                         \
        __half2 hp;                                                             \
        hp = __floats2half2_rn(sf[2*(j)][0],   sf[2*(j)][1]);   pf[0] = *(uint32_t*)&hp; \
        hp = __floats2half2_rn(sf[2*(j)][2],   sf[2*(j)][3]);   pf[1] = *(uint32_t*)&hp; \
        hp = __floats2half2_rn(sf[2*(j)+1][0], sf[2*(j)+1][1]); pf[2] = *(uint32_t*)&hp; \
        hp = __floats2half2_rn(sf[2*(j)+1][2], sf[2*(j)+1][3]); pf[3] = *(uint32_t*)&hp; \
        int row = (j) * 16 + vrow_b;                                            \
        _Pragma("unroll")                                                       \
        for (int dd = 0; dd < 8; dd += 2) {                                     \
            uint32_t so0 = (uint32_t)(row * AST + (dd    ) * 16 + vcol_b) * 2;  \
            uint32_t so1 = (uint32_t)(row * AST + (dd + 1) * 16 + vcol_b) * 2;  \
            uint32_t vh0[4], vh1[4];                                            \
            LDSM4T(vh0, sVh_u + so0);                                           \
            LDSM4T(vh1, sVh_u + so1);                                           \
            MMAH(o[2*dd],   pf, vh0[0], vh0[1]);                                \
            MMAH(o[2*dd+1], pf, vh0[2], vh0[3]);                                \
            MMAH(o[2*dd+2], pf, vh1[0], vh1[1]);                                \
            MMAH(o[2*dd+3], pf, vh1[2], vh1[3]);                                \
        }                                                                       \
    } while (0)

    if (DIAG) {
        for (int j = 0; j <= warp; j++)
            PV_BLOCK(j);
    } else {
        #pragma unroll
        for (int j = 0; j < 8; j++)
            PV_BLOCK(j);
    }
#undef PV_BLOCK
}

// ---------------------------------------------------------------------------
// Tensor-core causal flash attention
// ---------------------------------------------------------------------------
__global__ __launch_bounds__(256, 1)
void attn_mma_kernel()
{
    extern __shared__ char smem[];
    const uint32_t sbase = smem_u32(smem);

    const int tid  = threadIdx.x;
    const int lane = tid & 31;
    const int warp = tid >> 5;
    const int lrow = lane & 7;
    const int lq   = lane >> 3;
    const int qt   = (gridDim.x - 1) - blockIdx.x;
    const int bh   = blockIdx.y;
    const int q0   = qt * 128;
    const size_t base = (size_t)bh * S_ * HD;

    #pragma unroll
    for (int it = 0; it < 8; it++) {
        int idx = it * 256 + tid;
        int r   = idx >> 4;
        int c8  = (idx & 15) * 8;
        size_t g = base + (size_t)(q0 + r) * HD + c8;
        uint32_t so = (uint32_t)(r * AST + c8) * 2;
        CPA16(sbase + so,          (const char*)&g_qh[g]);
        CPA16(sbase + ATILE2 + so, (const char*)&g_ql[g]);
    }
    CPA_COMMIT();
    CPA_WAIT0();
    __syncthreads();

    uint32_t qfh[8][4], qfl[8][4];
    {
        int row = warp * 16 + ((lq & 1) ? 8 : 0) + lrow;
        #pragma unroll
        for (int ks = 0; ks < 8; ks++) {
            int col = ks * 16 + ((lq & 2) ? 8 : 0);
            uint32_t so = (uint32_t)(row * AST + col) * 2;
            LDSM4(qfh[ks], sbase + so);
            LDSM4(qfl[ks], sbase + ATILE2 + so);
        }
    }
    __syncthreads();

    float o[16][4];
    #pragma unroll
    for (int j = 0; j < 16; j++)
        #pragma unroll
        for (int e = 0; e < 4; e++) o[j][e] = 0.f;
    float mr[2] = { -1e30f, -1e30f };
    float lr_[2] = { 0.f, 0.f };

    const int krow_b = ((lq & 2) ? 8 : 0) + lrow;
    const int kcol_b = ((lq & 1) ? 8 : 0);
    const int vrow_b = ((lq & 1) ? 8 : 0) + lrow;
    const int vcol_b = ((lq & 2) ? 8 : 0);
    const int myrow  = lane >> 2;
    const int mycol  = 2 * (lane & 3);
    const int grow0  = q0 + warp * 16 + myrow;

    auto load_kv = [&](int buf, int kb) {
        uint32_t t0 = sbase + (uint32_t)(3 * buf) * ATILE2;
        #pragma unroll
        for (int it = 0; it < 8; it++) {
            int idx = it * 256 + tid;
            int r   = idx >> 4;
            int c8  = (idx & 15) * 8;
            size_t g = base + (size_t)(kb + r) * HD + c8;
            uint32_t so = (uint32_t)(r * AST + c8) * 2;
            CPA16(t0 + so,              (const char*)&g_kh[g]);
            CPA16(t0 + ATILE2 + so,     (const char*)&g_kl[g]);
            CPA16(t0 + 2 * ATILE2 + so, (const char*)&g_vh[g]);
        }
        CPA_COMMIT();
    };

    load_kv(0, 0);

    for (int kt = 0; kt < qt; kt++) {
        const int cur = kt & 1;
        load_kv(cur ^ 1, (kt + 1) * 128);
        CPA_WAIT1();
        __syncthreads();

        const uint32_t sKh_u = sbase + (uint32_t)(3 * cur) * ATILE2;
        attn_step<false>(sKh_u, sKh_u + ATILE2, sKh_u + 2 * ATILE2,
                         qfh, qfl, o, mr, lr_, warp,
                         krow_b, kcol_b, vrow_b, vcol_b,
                         myrow, mycol, kt * 128, grow0);
        __syncthreads();
    }

    CPA_WAIT0();
    __syncthreads();
    {
        const uint32_t sKh_u = sbase + (uint32_t)(3 * (qt & 1)) * ATILE2;
        attn_step<true>(sKh_u, sKh_u + ATILE2, sKh_u + 2 * ATILE2,
                        qfh, qfl, o, mr, lr_, warp,
                        krow_b, kcol_b, vrow_b, vcol_b,
                        myrow, mycol, qt * 128, grow0);
    }

    const int b = bh >> 4;
    const int h = bh & 15;
    float inv0 = 1.0f / lr_[0];
    float inv1 = 1.0f / lr_[1];
    const int srow = q0 + warp * 16 + myrow;
    #pragma unroll
    for (int j = 0; j < 16; j++) {
        int col = j * 8 + mycol;
        #pragma unroll
        for (int rr = 0; rr < 2; rr++) {
            float v0 = o[j][rr * 2]     * (rr ? inv1 : inv0);
            float v1 = o[j][rr * 2 + 1] * (rr ? inv1 : inv0);
            size_t off = ((size_t)(b * S_) + srow + rr * 8) * H_ + h * HD + col;
            *(__half2*)&g_cf[off] = __floats2half2_rn(v0, v1);
        }
    }
}

// ---------------------------------------------------------------------------
extern "C" void kernel_launch(void* const* d_in, const int* in_sizes, int n_in,
                              void* d_out, int out_size)
{
    (void)in_sizes; (void)n_in; (void)out_size;
    const float* x  = (const float*)d_in[0];
    const float* Wq = (const float*)d_in[1];
    const float* Wk = (const float*)d_in[2];
    const float* Wv = (const float*)d_in[3];
    const float* Wo = (const float*)d_in[4];
    const float* cs = (const float*)d_in[5];
    const float* sn = (const float*)d_in[6];
    float* out = (float*)d_out;

    prep_kernel<<<PREP_XB + 4 * PREP_WB, 256>>>(x, Wq, Wk, Wv, Wo);

    cudaFuncSetAttribute(qkv_mma_kernel,
                         cudaFuncAttributeMaxDynamicSharedMemorySize, OUT_SMEM);
    qkv_mma_kernel<<<dim3(H_ / 128, MTOT / 64, 3), 256, OUT_SMEM>>>(cs, sn);

    cudaFuncSetAttribute(attn_mma_kernel,
                         cudaFuncAttributeMaxDynamicSharedMemorySize, ATTN_SMEM);
    attn_mma_kernel<<<dim3(S_ / 128, B_ * NH), 256, ATTN_SMEM>>>();

    cudaFuncSetAttribute(outproj_mma_kernel,
                         cudaFuncAttributeMaxDynamicSharedMemorySize, OUT_SMEM);
    outproj_mma_kernel<<<dim3(H_ / 128, MTOT / 128), 256, OUT_SMEM>>>(out);
}

// round 17
// speedup vs baseline: 1.0150x; 1.0150x over previous
#include <cuda_runtime.h>
#include <cuda_bf16.h>
#include <cuda_fp16.h>
#include <cstdint>

#define B_    2
#define S_    2048
#define H_    2048
#define NH    16
#define HD    128
#define MTOT  (B_ * S_)           // 4096
#define SCALE 11.313708498984761f // sqrt(128)
#define HH    ((size_t)H_ * H_)

// 3-term GEMM tiling (BK=32, 2 CTAs/SM)
#define BK3     32
#define NCH3    (H_ / BK3)            // 64
#define TS3     40
#define TILE3B  (128 * TS3 * 2)       // 10240 B
#define BUF3B   (4 * TILE3B)          // 40960 B
#define GEMM_SMEM (2 * BUF3B)         // 81920 B

// 1-term GEMM tiling (BK=64, 2 CTAs/SM)
#define BK1     64
#define NCH1    (H_ / BK1)            // 32
#define TS1     72
#define TILE1B  (128 * TS1 * 2)       // 18432 B
#define BUF1B   (2 * TILE1B)          // 36864 B
#define OUT_SMEM (2 * BUF1B)          // 73728 B

// Attention smem
#define AST 136
#define ATILE  (128 * AST)
#define ATILE2 (ATILE * 2)
#define ATTN_SMEM (6 * ATILE2)        // 208896 B

// Prep: 8 floats per thread
#define PREP_XB ((MTOT * H_) / 2048)  // 4096
#define PREP_WB ((int)(HH / 2048))    // 2048

// ---------------------------------------------------------------------------
// Device scratch
// ---------------------------------------------------------------------------
__device__ __nv_bfloat16 g_xh[(size_t)MTOT * H_];
__device__ __nv_bfloat16 g_xl[(size_t)MTOT * H_];
__device__ __nv_bfloat16 g_wh[2ull * HH];
__device__ __nv_bfloat16 g_wl[2ull * HH];
__device__ __half g_xf [(size_t)MTOT * H_];
__device__ __half g_wvf[HH];
__device__ __half g_wof[HH];
__device__ __half g_cf [(size_t)MTOT * H_];
__device__ __half g_qh[(size_t)MTOT * H_];   // q*SCALE fp16 hi/lo (post-RoPE)
__device__ __half g_ql[(size_t)MTOT * H_];
__device__ __half g_kh[(size_t)MTOT * H_];
__device__ __half g_kl[(size_t)MTOT * H_];
__device__ __half g_vh[(size_t)MTOT * H_];

// ---------------------------------------------------------------------------
// PTX helpers
// ---------------------------------------------------------------------------
__device__ __forceinline__ uint32_t smem_u32(const void* p) {
    uint32_t a;
    asm("{ .reg .u64 t; cvta.to.shared.u64 t, %1; cvt.u32.u64 %0, t; }"
        : "=r"(a) : "l"(p));
    return a;
}

#define LDSM4(r, a) \
    asm volatile("ldmatrix.sync.aligned.m8n8.x4.shared.b16 {%0,%1,%2,%3}, [%4];" \
        : "=r"((r)[0]), "=r"((r)[1]), "=r"((r)[2]), "=r"((r)[3]) : "r"(a))
#define LDSM4T(r, a) \
    asm volatile("ldmatrix.sync.aligned.m8n8.x4.trans.shared.b16 {%0,%1,%2,%3}, [%4];" \
        : "=r"((r)[0]), "=r"((r)[1]), "=r"((r)[2]), "=r"((r)[3]) : "r"(a))

#define MMAB(d, a, b0v, b1v) \
    asm volatile("mma.sync.aligned.m16n8k16.row.col.f32.bf16.bf16.f32 " \
        "{%0,%1,%2,%3},{%4,%5,%6,%7},{%8,%9},{%0,%1,%2,%3};" \
        : "+f"((d)[0]), "+f"((d)[1]), "+f"((d)[2]), "+f"((d)[3]) \
        : "r"((a)[0]), "r"((a)[1]), "r"((a)[2]), "r"((a)[3]), \
          "r"(b0v), "r"(b1v))
#define MMAH(d, a, b0v, b1v) \
    asm volatile("mma.sync.aligned.m16n8k16.row.col.f32.f16.f16.f32 " \
        "{%0,%1,%2,%3},{%4,%5,%6,%7},{%8,%9},{%0,%1,%2,%3};" \
        : "+f"((d)[0]), "+f"((d)[1]), "+f"((d)[2]), "+f"((d)[3]) \
        : "r"((a)[0]), "r"((a)[1]), "r"((a)[2]), "r"((a)[3]), \
          "r"(b0v), "r"(b1v))

#define CPA16(dst, src) \
    asm volatile("cp.async.cg.shared.global [%0], [%1], 16;" \
        :: "r"(dst), "l"(src) : "memory")
#define CPA_COMMIT() asm volatile("cp.async.commit_group;" ::: "memory")
#define CPA_WAIT1()  asm volatile("cp.async.wait_group 1;" ::: "memory")
#define CPA_WAIT0()  asm volatile("cp.async.wait_group 0;" ::: "memory")

// ---------------------------------------------------------------------------
// 3-term split-bf16 GEMM (Q,K projections) — BK=32, 2 CTAs/SM
// ---------------------------------------------------------------------------
__device__ __forceinline__ void prefetch3(
    uint32_t sdst, const char* s0, const char* s1,
    const char* s2, const char* s3, int kc)
{
    const char* srcs[4] = { s0, s1, s2, s3 };
    const int tid = threadIdx.x;
    #pragma unroll
    for (int it = 0; it < 8; it++) {
        int idx  = it * 256 + tid;
        int tile = idx >> 9;
        int r    = (idx >> 2) & 127;
        int cv   = idx & 3;
        const char* src = srcs[tile] + (size_t)r * (H_ * 2) + kc * (BK3 * 2) + cv * 16;
        uint32_t dst = sdst + tile * TILE3B + (uint32_t)(r * TS3 + cv * 8) * 2;
        CPA16(dst, src);
    }
    CPA_COMMIT();
}

__device__ __forceinline__ void gemm_main3(
    const __nv_bfloat16* __restrict__ Ah, const __nv_bfloat16* __restrict__ Al,
    const __nv_bfloat16* __restrict__ Wh, const __nv_bfloat16* __restrict__ Wl,
    int m0, int n0, float acc[2][8][4])
{
    extern __shared__ char smx[];
    const uint32_t sbase = smem_u32(smx);
    const char* a0 = (const char*)(Ah + (size_t)m0 * H_);
    const char* a1 = (const char*)(Al + (size_t)m0 * H_);
    const char* b0 = (const char*)(Wh + (size_t)n0 * H_);
    const char* b1 = (const char*)(Wl + (size_t)n0 * H_);
    const int lane = threadIdx.x & 31;
    const int warp = threadIdx.x >> 5;
    const int wm = warp & 3;
    const int wn = warp >> 2;
    const int lrow = lane & 15;
    const int lk8  = (lane >> 4) * 8;

    prefetch3(sbase, a0, a1, b0, b1, 0);

    for (int c = 0; c < NCH3; c++) {
        const uint32_t sbuf = sbase + (uint32_t)(c & 1) * BUF3B;
        if (c + 1 < NCH3) {
            prefetch3(sbase + (uint32_t)((c + 1) & 1) * BUF3B, a0, a1, b0, b1, c + 1);
            CPA_WAIT1();
        } else {
            CPA_WAIT0();
        }
        __syncthreads();

        #pragma unroll
        for (int ks = 0; ks < 2; ks++) {
            const int koff = ks * 16 + lk8;
            uint32_t ah[2][4], al[2][4];
            #pragma unroll
            for (int g = 0; g < 2; g++) {
                uint32_t addr = sbuf +
                    (uint32_t)((wm * 32 + g * 16 + lrow) * TS3 + koff) * 2;
                LDSM4(ah[g], addr);
                LDSM4(al[g], addr + TILE3B);
            }
            const uint32_t bbase = sbuf + 2 * TILE3B +
                (uint32_t)((wn * 64 + lrow) * TS3 + koff) * 2;
            uint32_t bh[2][4];
            LDSM4(bh[0], bbase);
            #pragma unroll
            for (int nb = 0; nb < 4; nb++) {
                const int cur = nb & 1, nxt = cur ^ 1;
                const uint32_t baddr = bbase + (uint32_t)(nb * 16 * TS3) * 2;
                if (nb < 3)
                    LDSM4(bh[nxt], baddr + (uint32_t)(16 * TS3) * 2);
                MMAB(acc[0][2*nb],   ah[0], bh[cur][0], bh[cur][2]);
                MMAB(acc[0][2*nb+1], ah[0], bh[cur][1], bh[cur][3]);
                MMAB(acc[1][2*nb],   ah[1], bh[cur][0], bh[cur][2]);
                MMAB(acc[1][2*nb+1], ah[1], bh[cur][1], bh[cur][3]);
                uint32_t bl[4];
                LDSM4(bl, baddr + TILE3B);
                MMAB(acc[0][2*nb],   al[0], bh[cur][0], bh[cur][2]);
                MMAB(acc[0][2*nb+1], al[0], bh[cur][1], bh[cur][3]);
                MMAB(acc[1][2*nb],   al[1], bh[cur][0], bh[cur][2]);
                MMAB(acc[1][2*nb+1], al[1], bh[cur][1], bh[cur][3]);
                MMAB(acc[0][2*nb],   ah[0], bl[0], bl[2]);
                MMAB(acc[0][2*nb+1], ah[0], bl[1], bl[3]);
                MMAB(acc[1][2*nb],   ah[1], bl[0], bl[2]);
                MMAB(acc[1][2*nb+1], ah[1], bl[1], bl[3]);
            }
        }
        __syncthreads();
    }
}

// ---------------------------------------------------------------------------
// 1-term fp16 GEMM (V projection, output projection) — BK=64
// ---------------------------------------------------------------------------
__device__ __forceinline__ void prefetch1(
    uint32_t sdst, const char* s0, const char* s1, int kc)
{
    const char* srcs[2] = { s0, s1 };
    const int tid = threadIdx.x;
    #pragma unroll
    for (int it = 0; it < 8; it++) {
        int idx  = it * 256 + tid;
        int tile = idx >> 10;
        int r    = (idx >> 3) & 127;
        int cv   = idx & 7;
        const char* src = srcs[tile] + (size_t)r * (H_ * 2) + kc * (BK1 * 2) + cv * 16;
        uint32_t dst = sdst + tile * TILE1B + (uint32_t)(r * TS1 + cv * 8) * 2;
        CPA16(dst, src);
    }
    CPA_COMMIT();
}

__device__ __forceinline__ void gemm_main1(
    const __half* __restrict__ A, const __half* __restrict__ W,
    int m0, int n0, float acc[2][8][4])
{
    extern __shared__ char smx[];
    const uint32_t sbase = smem_u32(smx);
    const char* a0 = (const char*)(A + (size_t)m0 * H_);
    const char* b0 = (const char*)(W + (size_t)n0 * H_);
    const int lane = threadIdx.x & 31;
    const int warp = threadIdx.x >> 5;
    const int wm = warp & 3;
    const int wn = warp >> 2;
    const int lrow = lane & 15;
    const int lk8  = (lane >> 4) * 8;

    prefetch1(sbase, a0, b0, 0);

    for (int c = 0; c < NCH1; c++) {
        const uint32_t sbuf = sbase + (uint32_t)(c & 1) * BUF1B;
        if (c + 1 < NCH1) {
            prefetch1(sbase + (uint32_t)((c + 1) & 1) * BUF1B, a0, b0, c + 1);
            CPA_WAIT1();
        } else {
            CPA_WAIT0();
        }
        __syncthreads();

        #pragma unroll
        for (int ks = 0; ks < 4; ks++) {
            const int koff = ks * 16 + lk8;
            uint32_t ah[2][4];
            #pragma unroll
            for (int g = 0; g < 2; g++) {
                uint32_t addr = sbuf +
                    (uint32_t)((wm * 32 + g * 16 + lrow) * TS1 + koff) * 2;
                LDSM4(ah[g], addr);
            }
            const uint32_t bbase = sbuf + TILE1B +
                (uint32_t)((wn * 64 + lrow) * TS1 + koff) * 2;
            uint32_t bb[2][4];
            LDSM4(bb[0], bbase);
            #pragma unroll
            for (int nb = 0; nb < 4; nb++) {
                const int cur = nb & 1, nxt = cur ^ 1;
                if (nb < 3)
                    LDSM4(bb[nxt], bbase + (uint32_t)((nb + 1) * 16 * TS1) * 2);
                MMAH(acc[0][2*nb],   ah[0], bb[cur][0], bb[cur][2]);
                MMAH(acc[0][2*nb+1], ah[0], bb[cur][1], bb[cur][3]);
                MMAH(acc[1][2*nb],   ah[1], bb[cur][0], bb[cur][2]);
                MMAH(acc[1][2*nb+1], ah[1], bb[cur][1], bb[cur][3]);
            }
        }
        __syncthreads();
    }
}

__device__ __forceinline__ void acc_to_smem(float acc[2][8][4], float* smf)
{
    const int lane = threadIdx.x & 31;
    const int warp = threadIdx.x >> 5;
    const int wm = warp & 3, wn = warp >> 2;
    #pragma unroll
    for (int g = 0; g < 2; g++) {
        #pragma unroll
        for (int j = 0; j < 8; j++) {
            int row = wm * 32 + g * 16 + (lane >> 2);
            int col = wn * 64 + (j >> 1) * 16 + (j & 1) * 8 + 2 * (lane & 3);
            smf[row * 132 + col]           = acc[g][j][0];
            smf[row * 132 + col + 1]       = acc[g][j][1];
            smf[(row + 8) * 132 + col]     = acc[g][j][2];
            smf[(row + 8) * 132 + col + 1] = acc[g][j][3];
        }
    }
}

// ---------------------------------------------------------------------------
// Fused QKV projection (z = 0/1/2). z<2: 3-term bf16 GEMM + RoPE -> fp16
// hi/lo (q pre-scaled by sqrt(128)). z=2: 1-term fp16 GEMM -> v fp16.
// Single launch packs all 1536 blocks; cheap V tiles land in the tail wave.
// ---------------------------------------------------------------------------
__global__ __launch_bounds__(256, 2)
void qkv_mma_kernel(const float* __restrict__ cs, const float* __restrict__ sn)
{
    const int z    = blockIdx.z;
    const int head = blockIdx.x;
    const int m0   = blockIdx.y * 128;
    const int n0   = head * 128;

    float acc[2][8][4];
    #pragma unroll
    for (int g = 0; g < 2; g++)
        #pragma unroll
        for (int j = 0; j < 8; j++)
            #pragma unroll
            for (int e = 0; e < 4; e++) acc[g][j][e] = 0.f;

    if (z < 2) {
        gemm_main3(g_xh, g_xl, g_wh + (size_t)z * HH, g_wl + (size_t)z * HH,
                   m0, n0, acc);
    } else {
        gemm_main1(g_xf, g_wvf, m0, n0, acc);
    }

    extern __shared__ char smx[];
    float* smf = (float*)smx;   // 67584 <= 81920
    acc_to_smem(acc, smf);
    __syncthreads();

    const int t  = threadIdx.x;
    const int r  = t >> 1;
    const int dh = (t & 1) * 32;
    const int m  = m0 + r;
    const int s  = m & (S_ - 1);
    const int b  = m >> 11;
    const size_t rowbase = ((size_t)(b * NH + head) * S_ + s) * HD;

    if (z < 2) {
        __half* dsth = ((z == 0) ? g_qh : g_kh) + rowbase;
        __half* dstl = ((z == 0) ? g_ql : g_kl) + rowbase;
        const float sc = (z == 0) ? SCALE : 1.0f;
        const float* crow = cs + (size_t)s * HD;
        const float* srow = sn + (size_t)s * HD;
        #pragma unroll
        for (int j = 0; j < 32; j++) {
            float lo = smf[r * 132 + dh + j];
            float hi = smf[r * 132 + dh + j + 64];
            float olo = (lo * crow[dh + j]      - hi * srow[dh + j])      * sc;
            float ohi = (hi * crow[dh + j + 64] + lo * srow[dh + j + 64]) * sc;
            __half a  = __float2half_rn(olo);
            __half bq = __float2half_rn(ohi);
            dsth[dh + j]      = a;
            dsth[dh + j + 64] = bq;
            dstl[dh + j]      = __float2half_rn(olo - __half2float(a));
            dstl[dh + j + 64] = __float2half_rn(ohi - __half2float(bq));
        }
    } else {
        __half* dst = g_vh + rowbase;
        #pragma unroll
        for (int j = 0; j < 32; j++) {
            dst[dh + j]      = __float2half_rn(smf[r * 132 + dh + j]);
            dst[dh + j + 64] = __float2half_rn(smf[r * 132 + dh + j + 64]);
        }
    }
}

// ---------------------------------------------------------------------------
// Output projection
// ---------------------------------------------------------------------------
__global__ __launch_bounds__(256, 2)
void outproj_mma_kernel(float* __restrict__ out)
{
    const int m0 = blockIdx.y * 128;
    const int n0 = blockIdx.x * 128;

    float acc[2][8][4];
    #pragma unroll
    for (int g = 0; g < 2; g++)
        #pragma unroll
        for (int j = 0; j < 8; j++)
            #pragma unroll
            for (int e = 0; e < 4; e++) acc[g][j][e] = 0.f;

    gemm_main1(g_cf, g_wof, m0, n0, acc);

    const int lane = threadIdx.x & 31;
    const int warp = threadIdx.x >> 5;
    const int wm = warp & 3, wn = warp >> 2;
    #pragma unroll
    for (int g = 0; g < 2; g++) {
        #pragma unroll
        for (int j = 0; j < 8; j++) {
            size_t row = (size_t)m0 + wm * 32 + g * 16 + (lane >> 2);
            int col = n0 + wn * 64 + (j >> 1) * 16 + (j & 1) * 8 + 2 * (lane & 3);
            *(float2*)&out[row * H_ + col] =
                make_float2(acc[g][j][0], acc[g][j][1]);
            *(float2*)&out[(row + 8) * H_ + col] =
                make_float2(acc[g][j][2], acc[g][j][3]);
        }
    }
}

// ---------------------------------------------------------------------------
// Fused prep — 8 floats/thread, 16B stores per destination array
// ---------------------------------------------------------------------------
__global__ void prep_kernel(const float* __restrict__ x,
                            const float* __restrict__ Wq,
                            const float* __restrict__ Wk,
                            const float* __restrict__ Wv,
                            const float* __restrict__ Wo)
{
    const int bid = blockIdx.x;
    const int t   = threadIdx.x;

    union PB { __nv_bfloat16 b[8]; uint4 u; };
    union PH { __half h[8]; uint4 u; };

    if (bid < PREP_XB) {
        size_t i = (size_t)bid * 256 + t;
        float4 v0 = ((const float4*)x)[2 * i];
        float4 v1 = ((const float4*)x)[2 * i + 1];
        float f[8] = { v0.x, v0.y, v0.z, v0.w, v1.x, v1.y, v1.z, v1.w };
        PB ph, pl; PH pf;
        #pragma unroll
        for (int j = 0; j < 8; j++) {
            ph.b[j] = __float2bfloat16(f[j]);
            pl.b[j] = __float2bfloat16(f[j] - __bfloat162float(ph.b[j]));
            pf.h[j] = __float2half_rn(f[j]);
        }
        ((uint4*)g_xh)[i] = ph.u;
        ((uint4*)g_xl)[i] = pl.u;
        ((uint4*)g_xf)[i] = pf.u;
    } else if (bid < PREP_XB + 2 * PREP_WB) {
        int wsel = (bid - PREP_XB) / PREP_WB;          // 0=Wq, 1=Wk
        size_t i = (size_t)((bid - PREP_XB) % PREP_WB) * 256 + t;
        const float* W = wsel ? Wk : Wq;
        float4 v0 = ((const float4*)W)[2 * i];
        float4 v1 = ((const float4*)W)[2 * i + 1];
        float f[8] = { v0.x, v0.y, v0.z, v0.w, v1.x, v1.y, v1.z, v1.w };
        PB ph, pl;
        #pragma unroll
        for (int j = 0; j < 8; j++) {
            ph.b[j] = __float2bfloat16(f[j]);
            pl.b[j] = __float2bfloat16(f[j] - __bfloat162float(ph.b[j]));
        }
        size_t off = (size_t)wsel * (HH / 8);           // in uint4 units
        ((uint4*)g_wh)[off + i] = ph.u;
        ((uint4*)g_wl)[off + i] = pl.u;
    } else {
        int wsel = (bid - PREP_XB - 2 * PREP_WB) / PREP_WB;  // 0=Wv, 1=Wo
        size_t i = (size_t)((bid - PREP_XB - 2 * PREP_WB) % PREP_WB) * 256 + t;
        const float* W = wsel ? Wo : Wv;
        __half* dst = wsel ? g_wof : g_wvf;
        float4 v0 = ((const float4*)W)[2 * i];
        float4 v1 = ((const float4*)W)[2 * i + 1];
        PH pf;
        pf.h[0] = __float2half_rn(v0.x); pf.h[1] = __float2half_rn(v0.y);
        pf.h[2] = __float2half_rn(v0.z); pf.h[3] = __float2half_rn(v0.w);
        pf.h[4] = __float2half_rn(v1.x); pf.h[5] = __float2half_rn(v1.y);
        pf.h[6] = __float2half_rn(v1.z); pf.h[7] = __float2half_rn(v1.w);
        ((uint4*)dst)[i] = pf.u;
    }
}

// ---------------------------------------------------------------------------
// Attention step body (templated on diagonal handling)
// ---------------------------------------------------------------------------
template<bool DIAG>
__device__ __forceinline__ void attn_step(
    uint32_t sKh_u, uint32_t sKl_u, uint32_t sVh_u,
    uint32_t (&qfh)[8][4], uint32_t (&qfl)[8][4],
    float (&o)[16][4], float (&mr)[2], float (&lr_)[2],
    int warp, int krow_b, int kcol_b, int vrow_b, int vcol_b,
    int myrow, int mycol, int kb, int grow0)
{
    float sf[16][4];
    #pragma unroll
    for (int j = 0; j < 16; j++)
        #pragma unroll
        for (int e = 0; e < 4; e++) sf[j][e] = 0.f;

#define QK_BLOCK(jj, ks)                                                        \
    do {                                                                        \
        int col = (ks) * 16 + kcol_b;                                           \
        uint32_t so0 = (uint32_t)((((jj)    ) * 16 + krow_b) * AST + col) * 2;  \
        uint32_t so1 = (uint32_t)((((jj) + 1) * 16 + krow_b) * AST + col) * 2;  \
        uint32_t kfh0[4], kfl0[4], kfh1[4], kfl1[4];                            \
        LDSM4(kfh0, sKh_u + so0);                                               \
        LDSM4(kfh1, sKh_u + so1);                                               \
        LDSM4(kfl0, sKl_u + so0);                                               \
        LDSM4(kfl1, sKl_u + so1);                                               \
        MMAH(sf[2*(jj)],   qfh[ks], kfh0[0], kfh0[1]);                          \
        MMAH(sf[2*(jj)+1], qfh[ks], kfh0[2], kfh0[3]);                          \
        MMAH(sf[2*(jj)+2], qfh[ks], kfh1[0], kfh1[1]);                          \
        MMAH(sf[2*(jj)+3], qfh[ks], kfh1[2], kfh1[3]);                          \
        MMAH(sf[2*(jj)],   qfh[ks], kfl0[0], kfl0[1]);                          \
        MMAH(sf[2*(jj)+1], qfh[ks], kfl0[2], kfl0[3]);                          \
        MMAH(sf[2*(jj)+2], qfh[ks], kfl1[0], kfl1[1]);                          \
        MMAH(sf[2*(jj)+3], qfh[ks], kfl1[2], kfl1[3]);                          \
        MMAH(sf[2*(jj)],   qfl[ks], kfh0[0], kfh0[1]);                          \
        MMAH(sf[2*(jj)+1], qfl[ks], kfh0[2], kfh0[3]);                          \
        MMAH(sf[2*(jj)+2], qfl[ks], kfh1[0], kfh1[1]);                          \
        MMAH(sf[2*(jj)+3], qfl[ks], kfh1[2], kfh1[3]);                          \
    } while (0)

    if (DIAG) {
        #pragma unroll
        for (int ks = 0; ks < 8; ks++)
            for (int jj = 0; jj <= warp; jj += 2)
                QK_BLOCK(jj, ks);
    } else {
        #pragma unroll
        for (int ks = 0; ks < 8; ks++)
            #pragma unroll
            for (int jj = 0; jj < 8; jj += 2)
                QK_BLOCK(jj, ks);
    }
#undef QK_BLOCK

    #pragma unroll
    for (int rr = 0; rr < 2; rr++) {
        const int grow = grow0 + rr * 8;
        float mx = -1e30f;
        #pragma unroll
        for (int j = 0; j < 16; j++) {
            #pragma unroll
            for (int e = 0; e < 2; e++) {
                float v = sf[j][rr * 2 + e];
                if (DIAG && (kb + j * 8 + mycol + e) > grow) v = -1e30f;
                sf[j][rr * 2 + e] = v;
                mx = fmaxf(mx, v);
            }
        }
        mx = fmaxf(mx, __shfl_xor_sync(0xffffffffu, mx, 1));
        mx = fmaxf(mx, __shfl_xor_sync(0xffffffffu, mx, 2));
        float mnew  = fmaxf(mr[rr], mx);
        float alpha = __expf(mr[rr] - mnew);
        mr[rr] = mnew;
        float ls = 0.f;
        #pragma unroll
        for (int j = 0; j < 16; j++) {
            #pragma unroll
            for (int e = 0; e < 2; e++) {
                float p = __expf(sf[j][rr * 2 + e] - mnew);
                sf[j][rr * 2 + e] = p;
                ls += p;
            }
        }
        ls += __shfl_xor_sync(0xffffffffu, ls, 1);
        ls += __shfl_xor_sync(0xffffffffu, ls, 2);
        lr_[rr] = lr_[rr] * alpha + ls;
        #pragma unroll
        for (int j = 0; j < 16; j++) {
            o[j][rr * 2]     *= alpha;
            o[j][rr * 2 + 1] *= alpha;
        }
    }

#define PV_BLOCK(j)                                                             \
    do {                                                                        \
        uint32_t pf[4];                                                         \
        __half2 hp;                                                             \
        hp = __floats2half2_rn(sf[2*(j)][0],   sf[2*(j)][1]);   pf[0] = *(uint32_t*)&hp; \
        hp = __floats2half2_rn(sf[2*(j)][2],   sf[2*(j)][3]);   pf[1] = *(uint32_t*)&hp; \
        hp = __floats2half2_rn(sf[2*(j)+1][0], sf[2*(j)+1][1]); pf[2] = *(uint32_t*)&hp; \
        hp = __floats2half2_rn(sf[2*(j)+1][2], sf[2*(j)+1][3]); pf[3] = *(uint32_t*)&hp; \
        int row = (j) * 16 + vrow_b;                                            \
        _Pragma("unroll")                                                       \
        for (int dd = 0; dd < 8; dd += 2) {                                     \
            uint32_t so0 = (uint32_t)(row * AST + (dd    ) * 16 + vcol_b) * 2;  \
            uint32_t so1 = (uint32_t)(row * AST + (dd + 1) * 16 + vcol_b) * 2;  \
            uint32_t vh0[4], vh1[4];                                            \
            LDSM4T(vh0, sVh_u + so0);                                           \
            LDSM4T(vh1, sVh_u + so1);                                           \
            MMAH(o[2*dd],   pf, vh0[0], vh0[1]);                                \
            MMAH(o[2*dd+1], pf, vh0[2], vh0[3]);                                \
            MMAH(o[2*dd+2], pf, vh1[0], vh1[1]);                                \
            MMAH(o[2*dd+3], pf, vh1[2], vh1[3]);                                \
        }                                                                       \
    } while (0)

    if (DIAG) {
        for (int j = 0; j <= warp; j++)
            PV_BLOCK(j);
    } else {
        #pragma unroll
        for (int j = 0; j < 8; j++)
            PV_BLOCK(j);
    }
#undef PV_BLOCK
}

// ---------------------------------------------------------------------------
// Tensor-core causal flash attention
// ---------------------------------------------------------------------------
__global__ __launch_bounds__(256, 1)
void attn_mma_kernel()
{
    extern __shared__ char smem[];
    const uint32_t sbase = smem_u32(smem);

    const int tid  = threadIdx.x;
    const int lane = tid & 31;
    const int warp = tid >> 5;
    const int lrow = lane & 7;
    const int lq   = lane >> 3;
    const int qt   = (gridDim.x - 1) - blockIdx.x;
    const int bh   = blockIdx.y;
    const int q0   = qt * 128;
    const size_t base = (size_t)bh * S_ * HD;

    #pragma unroll
    for (int it = 0; it < 8; it++) {
        int idx = it * 256 + tid;
        int r   = idx >> 4;
        int c8  = (idx & 15) * 8;
        size_t g = base + (size_t)(q0 + r) * HD + c8;
        uint32_t so = (uint32_t)(r * AST + c8) * 2;
        CPA16(sbase + so,          (const char*)&g_qh[g]);
        CPA16(sbase + ATILE2 + so, (const char*)&g_ql[g]);
    }
    CPA_COMMIT();
    CPA_WAIT0();
    __syncthreads();

    uint32_t qfh[8][4], qfl[8][4];
    {
        int row = warp * 16 + ((lq & 1) ? 8 : 0) + lrow;
        #pragma unroll
        for (int ks = 0; ks < 8; ks++) {
            int col = ks * 16 + ((lq & 2) ? 8 : 0);
            uint32_t so = (uint32_t)(row * AST + col) * 2;
            LDSM4(qfh[ks], sbase + so);
            LDSM4(qfl[ks], sbase + ATILE2 + so);
        }
    }
    __syncthreads();

    float o[16][4];
    #pragma unroll
    for (int j = 0; j < 16; j++)
        #pragma unroll
        for (int e = 0; e < 4; e++) o[j][e] = 0.f;
    float mr[2] = { -1e30f, -1e30f };
    float lr_[2] = { 0.f, 0.f };

    const int krow_b = ((lq & 2) ? 8 : 0) + lrow;
    const int kcol_b = ((lq & 1) ? 8 : 0);
    const int vrow_b = ((lq & 1) ? 8 : 0) + lrow;
    const int vcol_b = ((lq & 2) ? 8 : 0);
    const int myrow  = lane >> 2;
    const int mycol  = 2 * (lane & 3);
    const int grow0  = q0 + warp * 16 + myrow;

    auto load_kv = [&](int buf, int kb) {
        uint32_t t0 = sbase + (uint32_t)(3 * buf) * ATILE2;
        #pragma unroll
        for (int it = 0; it < 8; it++) {
            int idx = it * 256 + tid;
            int r   = idx >> 4;
            int c8  = (idx & 15) * 8;
            size_t g = base + (size_t)(kb + r) * HD + c8;
            uint32_t so = (uint32_t)(r * AST + c8) * 2;
            CPA16(t0 + so,              (const char*)&g_kh[g]);
            CPA16(t0 + ATILE2 + so,     (const char*)&g_kl[g]);
            CPA16(t0 + 2 * ATILE2 + so, (const char*)&g_vh[g]);
        }
        CPA_COMMIT();
    };

    load_kv(0, 0);

    for (int kt = 0; kt < qt; kt++) {
        const int cur = kt & 1;
        load_kv(cur ^ 1, (kt + 1) * 128);
        CPA_WAIT1();
        __syncthreads();

        const uint32_t sKh_u = sbase + (uint32_t)(3 * cur) * ATILE2;
        attn_step<false>(sKh_u, sKh_u + ATILE2, sKh_u + 2 * ATILE2,
                         qfh, qfl, o, mr, lr_, warp,
                         krow_b, kcol_b, vrow_b, vcol_b,
                         myrow, mycol, kt * 128, grow0);
        __syncthreads();
    }

    CPA_WAIT0();
    __syncthreads();
    {
        const uint32_t sKh_u = sbase + (uint32_t)(3 * (qt & 1)) * ATILE2;
        attn_step<true>(sKh_u, sKh_u + ATILE2, sKh_u + 2 * ATILE2,
                        qfh, qfl, o, mr, lr_, warp,
                        krow_b, kcol_b, vrow_b, vcol_b,
                        myrow, mycol, qt * 128, grow0);
    }

    const int b = bh >> 4;
    const int h = bh & 15;
    float inv0 = 1.0f / lr_[0];
    float inv1 = 1.0f / lr_[1];
    const int srow = q0 + warp * 16 + myrow;
    #pragma unroll
    for (int j = 0; j < 16; j++) {
        int col = j * 8 + mycol;
        #pragma unroll
        for (int rr = 0; rr < 2; rr++) {
            float v0 = o[j][rr * 2]     * (rr ? inv1 : inv0);
            float v1 = o[j][rr * 2 + 1] * (rr ? inv1 : inv0);
            size_t off = ((size_t)(b * S_) + srow + rr * 8) * H_ + h * HD + col;
            *(__half2*)&g_cf[off] = __floats2half2_rn(v0, v1);
        }
    }
}

// ---------------------------------------------------------------------------
extern "C" void kernel_launch(void* const* d_in, const int* in_sizes, int n_in,
                              void* d_out, int out_size)
{
    (void)in_sizes; (void)n_in; (void)out_size;
    const float* x  = (const float*)d_in[0];
    const float* Wq = (const float*)d_in[1];
    const float* Wk = (const float*)d_in[2];
    const float* Wv = (const float*)d_in[3];
    const float* Wo = (const float*)d_in[4];
    const float* cs = (const float*)d_in[5];
    const float* sn = (const float*)d_in[6];
    float* out = (float*)d_out;

    prep_kernel<<<PREP_XB + 4 * PREP_WB, 256>>>(x, Wq, Wk, Wv, Wo);

    cudaFuncSetAttribute(qkv_mma_kernel,
                         cudaFuncAttributeMaxDynamicSharedMemorySize, GEMM_SMEM);
    qkv_mma_kernel<<<dim3(H_ / 128, MTOT / 128, 3), 256, GEMM_SMEM>>>(cs, sn);

    cudaFuncSetAttribute(attn_mma_kernel,
                         cudaFuncAttributeMaxDynamicSharedMemorySize, ATTN_SMEM);
    attn_mma_kernel<<<dim3(S_ / 128, B_ * NH), 256, ATTN_SMEM>>>();

    cudaFuncSetAttribute(outproj_mma_kernel,
                         cudaFuncAttributeMaxDynamicSharedMemorySize, OUT_SMEM);
    outproj_mma_kernel<<<dim3(H_ / 128, MTOT / 128), 256, OUT_SMEM>>>(out);
}